// round 1
// baseline (speedup 1.0000x reference)
#include <cuda_runtime.h>
#include <cstdint>

#define DEV_INLINE __device__ __forceinline__

constexpr int B_   = 4;
constexpr int K_   = 2048;
constexpr int P_   = 4096;
constexpr int NB   = 16;
constexpr int CIN  = 64;
constexpr int CMID = 32;
constexpr int FH   = 256;
constexpr int COUT = 128;
constexpr int GK   = B_ * K_;        // 8192 keys total
constexpr int EDIM = CMID * CIN;     // 2048

// Scratch (allocation-free rule: __device__ globals)
__device__ int   g_idx[GK * NB];
__device__ float g_E[(size_t)GK * EDIM];   // 64 MB
__device__ float g_H[(size_t)GK * FH];     // 8 MB

// ---------------------------------------------------------------------------
// Kernel 1: KNN — 1 warp per key, block = 8 warps (8 keys, same batch).
// Per-lane sorted top-16 (register compare-swap), warp merge by 16x arg-min.
// Distances computed in jax's exact order (mul/add, no fma) so the selected
// neighbor SET matches the reference top_k bitwise.
// ---------------------------------------------------------------------------
__global__ void __launch_bounds__(256) knn_kernel(
    const float* __restrict__ keys, const float* __restrict__ points)
{
    __shared__ float sp[P_ * 3];   // 48 KB points tile for this batch
    const int warp = threadIdx.x >> 5;
    const int lane = threadIdx.x & 31;
    const int g = blockIdx.x * 8 + warp;   // global key id
    const int b = g >> 11;                 // / 2048

    const float* pb = points + (size_t)b * P_ * 3;
    for (int i = threadIdx.x; i < P_ * 3; i += 256) sp[i] = pb[i];
    __syncthreads();

    const float kx = keys[g * 3 + 0];
    const float ky = keys[g * 3 + 1];
    const float kz = keys[g * 3 + 2];

    float bd[NB]; int bi[NB];
#pragma unroll
    for (int j = 0; j < NB; ++j) { bd[j] = 3.4e38f; bi[j] = 0x7fffffff; }

    for (int p = lane; p < P_; p += 32) {
        float dx = __fsub_rn(sp[p * 3 + 0], kx);
        float dy = __fsub_rn(sp[p * 3 + 1], ky);
        float dz = __fsub_rn(sp[p * 3 + 2], kz);
        float d  = __fadd_rn(__fadd_rn(__fmul_rn(dx, dx), __fmul_rn(dy, dy)),
                             __fmul_rn(dz, dz));
        if (d < bd[NB - 1]) {
            float cd = d; int ci = p;
#pragma unroll
            for (int j = 0; j < NB; ++j) {
                bool  sw = (cd < bd[j]);
                float tf = sw ? bd[j] : cd;
                int   ti = sw ? bi[j] : ci;
                bd[j] = sw ? cd : bd[j];
                bi[j] = sw ? ci : bi[j];
                cd = tf; ci = ti;
            }
        }
    }

    // Warp merge: 16 sequential arg-min extractions (tie -> lower point index,
    // matching jax.lax.top_k stability).
    int res_i = 0;
    for (int t = 0; t < NB; ++t) {
        float vd = bd[0]; int vi = bi[0]; int vl = lane;
#pragma unroll
        for (int off = 16; off > 0; off >>= 1) {
            float od = __shfl_xor_sync(0xffffffffu, vd, off);
            int   oi = __shfl_xor_sync(0xffffffffu, vi, off);
            int   ol = __shfl_xor_sync(0xffffffffu, vl, off);
            if (od < vd || (od == vd && oi < vi)) { vd = od; vi = oi; vl = ol; }
        }
        if (lane == t) res_i = vi;
        if (lane == vl) {   // pop my head
#pragma unroll
            for (int j = 0; j < NB - 1; ++j) { bd[j] = bd[j + 1]; bi[j] = bi[j + 1]; }
            bd[NB - 1] = 3.4e38f; bi[NB - 1] = 0x7fffffff;
        }
    }
    if (lane < NB) g_idx[g * NB + lane] = res_i;
}

// ---------------------------------------------------------------------------
// Kernel 2: per-edge weight MLP (3->32->32->32) + aggregation m^T f -> E.
// 1 warp per key, 4 warps per block. Lanes 0-15: MLP for neighbor n=lane.
// Lanes 16-31: gather neighbor features into smem (overlapped).
// ---------------------------------------------------------------------------
__global__ void __launch_bounds__(128) edge_kernel(
    const float* __restrict__ keys, const float* __restrict__ points,
    const float* __restrict__ feats,
    const float* __restrict__ w0, const float* __restrict__ b0,
    const float* __restrict__ w1, const float* __restrict__ b1,
    const float* __restrict__ w2, const float* __restrict__ b2)
{
    __shared__ __align__(16) float sw0[3][32];
    __shared__ float sb0[32], sb1[32], sb2[32];
    __shared__ __align__(16) float sw1t[32][32];   // transposed [out][in]
    __shared__ __align__(16) float sw2t[32][32];
    __shared__ __align__(16) float sm_m[4][NB][32];
    __shared__ __align__(16) float sm_f[4][NB][CIN];

    const int t = threadIdx.x;
    const int w = t >> 5, lane = t & 31;

    for (int i = t; i < 96; i += 128) sw0[i / 32][i % 32] = w0[i];
    if (t < 32) { sb0[t] = b0[t]; sb1[t] = b1[t]; sb2[t] = b2[t]; }
    for (int i = t; i < 1024; i += 128) {
        sw1t[i % 32][i / 32] = w1[i];
        sw2t[i % 32][i / 32] = w2[i];
    }
    __syncthreads();

    const int g = blockIdx.x * 4 + w;
    const int b = g >> 11;

    if (lane < NB) {
        const int n  = lane;
        const int gi = g_idx[g * NB + n];
        const float rx = points[((size_t)b * P_ + gi) * 3 + 0] - keys[g * 3 + 0];
        const float ry = points[((size_t)b * P_ + gi) * 3 + 1] - keys[g * 3 + 1];
        const float rz = points[((size_t)b * P_ + gi) * 3 + 2] - keys[g * 3 + 2];

        float h1[32];
#pragma unroll
        for (int j = 0; j < 32; ++j)
            h1[j] = fmaxf(fmaf(rx, sw0[0][j], fmaf(ry, sw0[1][j],
                          fmaf(rz, sw0[2][j], sb0[j]))), 0.0f);

        float h2[32];
#pragma unroll
        for (int j = 0; j < 32; ++j) {
            float a = sb1[j];
            const float4* wr = (const float4*)sw1t[j];
#pragma unroll
            for (int q = 0; q < 8; ++q) {
                float4 wv = wr[q];
                a = fmaf(h1[4 * q + 0], wv.x, a);
                a = fmaf(h1[4 * q + 1], wv.y, a);
                a = fmaf(h1[4 * q + 2], wv.z, a);
                a = fmaf(h1[4 * q + 3], wv.w, a);
            }
            h2[j] = fmaxf(a, 0.0f);
        }
#pragma unroll
        for (int j = 0; j < 32; ++j) {
            float a = sb2[j];
            const float4* wr = (const float4*)sw2t[j];
#pragma unroll
            for (int q = 0; q < 8; ++q) {
                float4 wv = wr[q];
                a = fmaf(h2[4 * q + 0], wv.x, a);
                a = fmaf(h2[4 * q + 1], wv.y, a);
                a = fmaf(h2[4 * q + 2], wv.z, a);
                a = fmaf(h2[4 * q + 3], wv.w, a);
            }
            sm_m[w][n][j] = a;   // linear output, no relu
        }
    } else {
        const int n  = lane - NB;
        const int gi = g_idx[g * NB + n];
        const float4* src = (const float4*)(feats + ((size_t)b * P_ + gi) * CIN);
        float4* dst = (float4*)sm_f[w][n];
#pragma unroll
        for (int i = 0; i < CIN / 4; ++i) dst[i] = src[i];
    }
    __syncwarp();

    // Aggregation: e[mc][ci] = sum_n m[n][mc] * f[n][ci].
    // Lane handles columns ci = lane and lane+32, all 32 mc rows.
    float e0[32], e1[32];
#pragma unroll
    for (int j = 0; j < 32; ++j) { e0[j] = 0.0f; e1[j] = 0.0f; }

#pragma unroll
    for (int n = 0; n < NB; ++n) {
        const float f0 = sm_f[w][n][lane];
        const float f1 = sm_f[w][n][lane + 32];
        const float4* mp = (const float4*)sm_m[w][n];
#pragma unroll
        for (int q = 0; q < 8; ++q) {
            float4 mv = mp[q];
            e0[4 * q + 0] = fmaf(mv.x, f0, e0[4 * q + 0]);
            e1[4 * q + 0] = fmaf(mv.x, f1, e1[4 * q + 0]);
            e0[4 * q + 1] = fmaf(mv.y, f0, e0[4 * q + 1]);
            e1[4 * q + 1] = fmaf(mv.y, f1, e1[4 * q + 1]);
            e0[4 * q + 2] = fmaf(mv.z, f0, e0[4 * q + 2]);
            e1[4 * q + 2] = fmaf(mv.z, f1, e1[4 * q + 2]);
            e0[4 * q + 3] = fmaf(mv.w, f0, e0[4 * q + 3]);
            e1[4 * q + 3] = fmaf(mv.w, f1, e1[4 * q + 3]);
        }
    }

    float* Eg = g_E + (size_t)g * EDIM;
#pragma unroll
    for (int mc = 0; mc < 32; ++mc) {
        Eg[mc * 64 + lane]      = e0[mc];
        Eg[mc * 64 + 32 + lane] = e1[mc];
    }
}

// ---------------------------------------------------------------------------
// Tiled fp32 GEMM with packed fma.rn.f32x2 inner loop (2x fp32 FMA rate;
// ptxas never emits FFMA2 from C++). C = act(A[M,K] @ B[K,N] + bias).
// ---------------------------------------------------------------------------
template <int BM, int BN, int BK, int TM, int TN, bool RELU>
DEV_INLINE void gemm_body(const float* __restrict__ A, const float* __restrict__ Bw,
                          const float* __restrict__ bias, float* __restrict__ C,
                          int M, int N, int Kd)
{
    constexpr int THREADS = (BM / TM) * (BN / TN);
    constexpr int LDA = BM + 4;   // pad: keeps 16B alignment (132*4, 68*4 both %16==0)
    __shared__ __align__(16) float As[BK][LDA];
    __shared__ __align__(16) float Bs[BK][BN];

    const int t  = threadIdx.x;
    const int tx = t % (BN / TN);
    const int ty = t / (BN / TN);
    const int m0 = blockIdx.y * BM;
    const int n0 = blockIdx.x * BN;

    constexpr int AV = (BM * BK / 4) / THREADS;
    constexpr int BV = (BK * BN / 4) / THREADS;

    float4 aR[AV], bR[BV];
    int aRow[AV], aCol[AV], bRow[BV], bCol[BV];
#pragma unroll
    for (int i = 0; i < AV; ++i) {
        int id = t + i * THREADS; aRow[i] = id / (BK / 4); aCol[i] = id % (BK / 4);
    }
#pragma unroll
    for (int i = 0; i < BV; ++i) {
        int id = t + i * THREADS; bRow[i] = id / (BN / 4); bCol[i] = id % (BN / 4);
    }

    auto gload = [&](int k0) {
#pragma unroll
        for (int i = 0; i < AV; ++i)
            aR[i] = *(const float4*)&A[(size_t)(m0 + aRow[i]) * Kd + k0 + aCol[i] * 4];
#pragma unroll
        for (int i = 0; i < BV; ++i)
            bR[i] = *(const float4*)&Bw[(size_t)(k0 + bRow[i]) * N + n0 + bCol[i] * 4];
    };
    auto sstore = [&]() {
#pragma unroll
        for (int i = 0; i < AV; ++i) {
            As[aCol[i] * 4 + 0][aRow[i]] = aR[i].x;
            As[aCol[i] * 4 + 1][aRow[i]] = aR[i].y;
            As[aCol[i] * 4 + 2][aRow[i]] = aR[i].z;
            As[aCol[i] * 4 + 3][aRow[i]] = aR[i].w;
        }
#pragma unroll
        for (int i = 0; i < BV; ++i)
            *(float4*)&Bs[bRow[i]][bCol[i] * 4] = bR[i];
    };

    unsigned long long acc[TM][TN / 2];
#pragma unroll
    for (int i = 0; i < TM; ++i)
#pragma unroll
        for (int j = 0; j < TN / 2; ++j) acc[i][j] = 0ull;

    auto compute = [&]() {
#pragma unroll
        for (int k = 0; k < BK; ++k) {
            float aF[TM];
#pragma unroll
            for (int v = 0; v < TM / 4; ++v) {
                float4 tmp = *(const float4*)&As[k][ty * TM + v * 4];
                aF[v * 4 + 0] = tmp.x; aF[v * 4 + 1] = tmp.y;
                aF[v * 4 + 2] = tmp.z; aF[v * 4 + 3] = tmp.w;
            }
            unsigned long long bP[TN / 2];
#pragma unroll
            for (int v = 0; v < TN / 4; ++v) {
                ulonglong2 tmp = *(const ulonglong2*)&Bs[k][tx * TN + v * 4];
                bP[v * 2] = tmp.x; bP[v * 2 + 1] = tmp.y;
            }
#pragma unroll
            for (int i = 0; i < TM; ++i) {
                unsigned long long aa;
                asm("mov.b64 %0, {%1, %1};" : "=l"(aa) : "r"(__float_as_uint(aF[i])));
#pragma unroll
                for (int j = 0; j < TN / 2; ++j)
                    asm("fma.rn.f32x2 %0, %1, %2, %0;"
                        : "+l"(acc[i][j]) : "l"(aa), "l"(bP[j]));
            }
        }
    };

    gload(0);
    sstore();
    __syncthreads();
    for (int k0 = BK; k0 < Kd; k0 += BK) {
        gload(k0);       // prefetch next tile to registers
        compute();       // compute on current smem tile
        __syncthreads();
        sstore();
        __syncthreads();
    }
    compute();

    float bia[TN];
#pragma unroll
    for (int j = 0; j < TN; ++j) bia[j] = bias[n0 + tx * TN + j];
#pragma unroll
    for (int i = 0; i < TM; ++i) {
        float outv[TN];
#pragma unroll
        for (int j = 0; j < TN / 2; ++j) {
            float lo = __uint_as_float((unsigned)(acc[i][j] & 0xffffffffull));
            float hi = __uint_as_float((unsigned)(acc[i][j] >> 32));
            outv[2 * j]     = lo + bia[2 * j];
            outv[2 * j + 1] = hi + bia[2 * j + 1];
        }
        if (RELU) {
#pragma unroll
            for (int j = 0; j < TN; ++j) outv[j] = fmaxf(outv[j], 0.0f);
        }
        float* cp = &C[(size_t)(m0 + ty * TM + i) * N + n0 + tx * TN];
#pragma unroll
        for (int v = 0; v < TN / 4; ++v)
            *(float4*)&cp[v * 4] = make_float4(outv[v * 4 + 0], outv[v * 4 + 1],
                                               outv[v * 4 + 2], outv[v * 4 + 3]);
    }
}

__global__ void __launch_bounds__(256) gemm1_kernel(const float* __restrict__ W,
                                                    const float* __restrict__ bias)
{
    gemm_body<128, 128, 16, 8, 8, true>(g_E, W, bias, g_H, GK, FH, EDIM);
}

__global__ void __launch_bounds__(256) gemm2_kernel(const float* __restrict__ W,
                                                    const float* __restrict__ bias,
                                                    float* __restrict__ C)
{
    gemm_body<64, 128, 16, 4, 8, false>(g_H, W, bias, C, GK, COUT, FH);
}

// ---------------------------------------------------------------------------
extern "C" void kernel_launch(void* const* d_in, const int* in_sizes, int n_in,
                              void* d_out, int out_size)
{
    const float* keys   = (const float*)d_in[0];
    const float* points = (const float*)d_in[1];
    const float* feats  = (const float*)d_in[2];
    const float* wc0W   = (const float*)d_in[3];
    const float* wc0b   = (const float*)d_in[4];
    const float* wc1W   = (const float*)d_in[5];
    const float* wc1b   = (const float*)d_in[6];
    const float* wc2W   = (const float*)d_in[7];
    const float* wc2b   = (const float*)d_in[8];
    const float* fc0W   = (const float*)d_in[9];
    const float* fc0b   = (const float*)d_in[10];
    const float* fc1W   = (const float*)d_in[11];
    const float* fc1b   = (const float*)d_in[12];
    float* out = (float*)d_out;

    knn_kernel<<<GK / 8, 256>>>(keys, points);
    edge_kernel<<<GK / 4, 128>>>(keys, points, feats,
                                 wc0W, wc0b, wc1W, wc1b, wc2W, wc2b);
    gemm1_kernel<<<dim3(FH / 128, GK / 128), 256>>>(fc0W, fc0b);
    gemm2_kernel<<<dim3(COUT / 128, GK / 64), 256>>>(fc1W, fc1b, out);
}